// round 1
// baseline (speedup 1.0000x reference)
#include <cuda_runtime.h>
#include <cuda_bf16.h>

// Problem constants
#define BATCH 256
#define SEQ   196
#define CH    768
#define NH    12
#define HD    64
#define M_ROWS (BATCH * SEQ)       // 50176
#define THREE_C (3 * CH)           // 2304
#define SCALE 0.125f               // 64^-0.5

// Scratch (static __device__ allocation — allowed)
__device__ float g_q[(size_t)BATCH * NH * SEQ * HD];   // [B,H,N,hd]
__device__ float g_k[(size_t)BATCH * NH * SEQ * HD];
__device__ float g_v[(size_t)BATCH * NH * SEQ * HD];
__device__ float g_rpb[(size_t)NH * SEQ * SEQ];        // [H,N,N]
__device__ float g_att[(size_t)M_ROWS * CH];           // [B,N,C] pre-proj

// ---------------------------------------------------------------------------
// SGEMM tiling parameters: C[M,N] = A[M,K] @ B[N,K]^T   (both row-major)
// ---------------------------------------------------------------------------
#define BM 128
#define BN 128
#define BK 16
#define TM 8
#define TN 8
#define PAD 4   // smem row padding to break store conflicts

// ---------------------------------------------------------------------------
// Kernel 1: fused QKV projection.
//   qkv = X @ W^T (+bias); split into q (scaled, +q_bias), k, v (+v_bias)
//   written in [B,H,N,hd] layout.
// ---------------------------------------------------------------------------
__global__ __launch_bounds__(256)
void qkv_gemm_kernel(const float* __restrict__ X,   // [M_ROWS, CH]
                     const float* __restrict__ W,   // [THREE_C, CH]
                     const float* __restrict__ qb,  // [CH]
                     const float* __restrict__ vb)  // [CH]
{
    __shared__ float As[BK][BM + PAD];
    __shared__ float Bs[BK][BN + PAD];

    const int bn = blockIdx.x;           // over THREE_C/BN = 18
    const int bm = blockIdx.y;           // over M_ROWS/BN = 392
    const int tid = threadIdx.x;

    const int loadRow  = tid >> 2;          // 0..63
    const int loadCol  = (tid & 3) * 4;     // 0,4,8,12

    const int threadRow = tid >> 4;         // 0..15
    const int threadCol = tid & 15;         // 0..15

    const float* Aptr = X + (size_t)(bm * BM) * CH;
    const float* Bptr = W + (size_t)(bn * BN) * CH;

    float acc[TM][TN];
    #pragma unroll
    for (int m = 0; m < TM; m++)
        #pragma unroll
        for (int n = 0; n < TN; n++) acc[m][n] = 0.f;

    for (int k0 = 0; k0 < CH; k0 += BK) {
        // load A tile (transposed into As[k][m])
        #pragma unroll
        for (int r = 0; r < 2; r++) {
            const int row = loadRow + r * 64;
            float4 va = *(const float4*)(Aptr + (size_t)row * CH + k0 + loadCol);
            As[loadCol + 0][row] = va.x;
            As[loadCol + 1][row] = va.y;
            As[loadCol + 2][row] = va.z;
            As[loadCol + 3][row] = va.w;
            float4 vb4 = *(const float4*)(Bptr + (size_t)row * CH + k0 + loadCol);
            Bs[loadCol + 0][row] = vb4.x;
            Bs[loadCol + 1][row] = vb4.y;
            Bs[loadCol + 2][row] = vb4.z;
            Bs[loadCol + 3][row] = vb4.w;
        }
        __syncthreads();

        #pragma unroll
        for (int kk = 0; kk < BK; kk++) {
            float ra[TM], rb[TN];
            #pragma unroll
            for (int m = 0; m < TM; m++) ra[m] = As[kk][threadRow * TM + m];
            #pragma unroll
            for (int n = 0; n < TN; n++) rb[n] = Bs[kk][threadCol * TN + n];
            #pragma unroll
            for (int m = 0; m < TM; m++)
                #pragma unroll
                for (int n = 0; n < TN; n++)
                    acc[m][n] = fmaf(ra[m], rb[n], acc[m][n]);
        }
        __syncthreads();
    }

    // Epilogue: scatter into q/k/v in [B,H,N,hd] layout.
    const int jbase = bn * BN + threadCol * TN;   // 8 consecutive output cols
    const int which = jbase / CH;                 // 0=q,1=k,2=v
    const int cbase = jbase % CH;
    const int h  = cbase / HD;
    const int d0 = cbase % HD;                    // 8 cols stay in one head

    #pragma unroll
    for (int m = 0; m < TM; m++) {
        const int i = bm * BM + threadRow * TM + m;
        const int b = i / SEQ;
        const int n = i % SEQ;
        const size_t base = (((size_t)(b * NH + h)) * SEQ + n) * HD + d0;
        if (which == 0) {
            float* dst = g_q + base;
            #pragma unroll
            for (int t = 0; t < TN; t++)
                dst[t] = (acc[m][t] + qb[cbase + t]) * SCALE;
        } else if (which == 1) {
            float* dst = g_k + base;
            #pragma unroll
            for (int t = 0; t < TN; t++)
                dst[t] = acc[m][t];
        } else {
            float* dst = g_v + base;
            #pragma unroll
            for (int t = 0; t < TN; t++)
                dst[t] = acc[m][t] + vb[cbase + t];
        }
    }
}

// ---------------------------------------------------------------------------
// Kernel 2: relative position bias gather  rpb[h,i,j] = table[rel_index[i,j], h]
// ---------------------------------------------------------------------------
__global__ void rpb_gather_kernel(const float* __restrict__ table, // [729, NH]
                                  const int* __restrict__ relidx)  // [SEQ*SEQ]
{
    int idx = blockIdx.x * blockDim.x + threadIdx.x;
    const int total = NH * SEQ * SEQ;
    if (idx >= total) return;
    int ij = idx % (SEQ * SEQ);
    int h  = idx / (SEQ * SEQ);
    g_rpb[idx] = table[relidx[ij] * NH + h];
}

// ---------------------------------------------------------------------------
// Kernel 3: attention per (b,h). K,V in smem; one thread per query row.
// ---------------------------------------------------------------------------
__global__ __launch_bounds__(224, 1)
void attn_kernel()
{
    extern __shared__ float smem[];
    float* Ks = smem;                 // [SEQ][HD]
    float* Vs = smem + SEQ * HD;      // [SEQ][HD]

    const int bh = blockIdx.x;        // b*NH + h
    const int b = bh / NH;
    const int h = bh % NH;
    const int tid = threadIdx.x;

    const float* Kg = g_k + (size_t)bh * SEQ * HD;
    const float* Vg = g_v + (size_t)bh * SEQ * HD;

    // stage K, V (3136 float4 each)
    for (int t = tid; t < (SEQ * HD) / 4; t += 224) {
        ((float4*)Ks)[t] = ((const float4*)Kg)[t];
        ((float4*)Vs)[t] = ((const float4*)Vg)[t];
    }
    __syncthreads();

    if (tid >= SEQ) return;

    // query row into registers
    float qr[HD];
    const float* Qg = g_q + (size_t)bh * SEQ * HD + (size_t)tid * HD;
    #pragma unroll
    for (int d = 0; d < HD; d += 4) {
        float4 v = *(const float4*)(Qg + d);
        qr[d] = v.x; qr[d+1] = v.y; qr[d+2] = v.z; qr[d+3] = v.w;
    }

    const float* rpb = g_rpb + (size_t)h * SEQ * SEQ + (size_t)tid * SEQ;

    // pass 1: scores + rowmax
    float s[SEQ];
    float mx = -1e30f;
    for (int j = 0; j < SEQ; j++) {
        const float* kj = Ks + j * HD;
        float a = rpb[j];
        #pragma unroll
        for (int d = 0; d < HD; d++) a = fmaf(qr[d], kj[d], a);
        s[j] = a;
        mx = fmaxf(mx, a);
    }

    // pass 2: exp + PV accumulate
    float o[HD];
    #pragma unroll
    for (int d = 0; d < HD; d++) o[d] = 0.f;
    float l = 0.f;
    for (int j = 0; j < SEQ; j++) {
        float p = __expf(s[j] - mx);
        l += p;
        const float* vj = Vs + j * HD;
        #pragma unroll
        for (int d = 0; d < HD; d++) o[d] = fmaf(p, vj[d], o[d]);
    }
    const float inv = 1.f / l;

    float* outp = g_att + ((size_t)(b * SEQ + tid)) * CH + h * HD;
    #pragma unroll
    for (int d = 0; d < HD; d += 4) {
        float4 v;
        v.x = o[d] * inv; v.y = o[d+1] * inv;
        v.z = o[d+2] * inv; v.w = o[d+3] * inv;
        *(float4*)(outp + d) = v;
    }
}

// ---------------------------------------------------------------------------
// Kernel 4: output projection  out = att @ proj_w^T + proj_b
// ---------------------------------------------------------------------------
__global__ __launch_bounds__(256)
void proj_gemm_kernel(const float* __restrict__ W,   // [CH, CH]
                      const float* __restrict__ pb,  // [CH]
                      float* __restrict__ out)       // [M_ROWS, CH]
{
    __shared__ float As[BK][BM + PAD];
    __shared__ float Bs[BK][BN + PAD];

    const int bn = blockIdx.x;          // CH/BN = 6
    const int bm = blockIdx.y;          // 392
    const int tid = threadIdx.x;

    const int loadRow = tid >> 2;
    const int loadCol = (tid & 3) * 4;
    const int threadRow = tid >> 4;
    const int threadCol = tid & 15;

    const float* Aptr = g_att + (size_t)(bm * BM) * CH;
    const float* Bptr = W + (size_t)(bn * BN) * CH;

    float acc[TM][TN];
    #pragma unroll
    for (int m = 0; m < TM; m++)
        #pragma unroll
        for (int n = 0; n < TN; n++) acc[m][n] = 0.f;

    for (int k0 = 0; k0 < CH; k0 += BK) {
        #pragma unroll
        for (int r = 0; r < 2; r++) {
            const int row = loadRow + r * 64;
            float4 va = *(const float4*)(Aptr + (size_t)row * CH + k0 + loadCol);
            As[loadCol + 0][row] = va.x;
            As[loadCol + 1][row] = va.y;
            As[loadCol + 2][row] = va.z;
            As[loadCol + 3][row] = va.w;
            float4 vb4 = *(const float4*)(Bptr + (size_t)row * CH + k0 + loadCol);
            Bs[loadCol + 0][row] = vb4.x;
            Bs[loadCol + 1][row] = vb4.y;
            Bs[loadCol + 2][row] = vb4.z;
            Bs[loadCol + 3][row] = vb4.w;
        }
        __syncthreads();

        #pragma unroll
        for (int kk = 0; kk < BK; kk++) {
            float ra[TM], rb[TN];
            #pragma unroll
            for (int m = 0; m < TM; m++) ra[m] = As[kk][threadRow * TM + m];
            #pragma unroll
            for (int n = 0; n < TN; n++) rb[n] = Bs[kk][threadCol * TN + n];
            #pragma unroll
            for (int m = 0; m < TM; m++)
                #pragma unroll
                for (int n = 0; n < TN; n++)
                    acc[m][n] = fmaf(ra[m], rb[n], acc[m][n]);
        }
        __syncthreads();
    }

    const int jbase = bn * BN + threadCol * TN;
    #pragma unroll
    for (int m = 0; m < TM; m++) {
        const int i = bm * BM + threadRow * TM + m;
        float* dst = out + (size_t)i * CH + jbase;
        #pragma unroll
        for (int t = 0; t < TN; t++)
            dst[t] = acc[m][t] + pb[jbase + t];
    }
}

// ---------------------------------------------------------------------------
// Launch
// ---------------------------------------------------------------------------
extern "C" void kernel_launch(void* const* d_in, const int* in_sizes, int n_in,
                              void* d_out, int out_size)
{
    const float* x       = (const float*)d_in[0];
    const float* qkv_w   = (const float*)d_in[1];
    const float* q_bias  = (const float*)d_in[2];
    const float* v_bias  = (const float*)d_in[3];
    const float* rpb_tab = (const float*)d_in[4];
    const float* proj_w  = (const float*)d_in[5];
    const float* proj_b  = (const float*)d_in[6];
    const int*   relidx  = (const int*)d_in[7];
    float*       out     = (float*)d_out;

    // 1. QKV projection
    {
        dim3 grid(THREE_C / BN, M_ROWS / BM);
        qkv_gemm_kernel<<<grid, 256>>>(x, qkv_w, q_bias, v_bias);
    }
    // 2. RPB gather
    {
        const int total = NH * SEQ * SEQ;
        rpb_gather_kernel<<<(total + 255) / 256, 256>>>(rpb_tab, relidx);
    }
    // 3. Attention
    {
        const int smem_bytes = 2 * SEQ * HD * sizeof(float); // 100352
        cudaFuncSetAttribute(attn_kernel,
                             cudaFuncAttributeMaxDynamicSharedMemorySize,
                             smem_bytes);
        attn_kernel<<<BATCH * NH, 224, smem_bytes>>>();
    }
    // 4. Projection
    {
        dim3 grid(CH / BN, M_ROWS / BM);
        proj_gemm_kernel<<<grid, 256>>>(proj_w, proj_b, out);
    }
}

// round 2
// speedup vs baseline: 1.1653x; 1.1653x over previous
#include <cuda_runtime.h>
#include <cuda_bf16.h>
#include <mma.h>

using namespace nvcuda;

// Problem constants
#define BATCH 256
#define SEQ   196
#define CH    768
#define NH    12
#define HD    64
#define M_ROWS (BATCH * SEQ)       // 50176
#define THREE_C (3 * CH)           // 2304
#define SCALE 0.125f               // 64^-0.5

// Scratch
__device__ float g_q[(size_t)BATCH * NH * SEQ * HD];   // [B,H,N,hd]
__device__ float g_k[(size_t)BATCH * NH * SEQ * HD];
__device__ float g_v[(size_t)BATCH * NH * SEQ * HD];
__device__ float g_rpb[(size_t)NH * SEQ * SEQ];        // [H,N,N]
__device__ float g_att[(size_t)M_ROWS * CH];           // [B,N,C] pre-proj

// ---------------------------------------------------------------------------
// TF32 WMMA GEMM: C[M,N] = A[M,K] @ B[N,K]^T  (A,B row-major)
// Block tile 128x128, K-tile 32. 8 warps, each computes 32x64
// (2 m-tiles x 4 n-tiles of 16x16).
// ---------------------------------------------------------------------------
#define BM 128
#define BN 128
#define BKO 32
#define LDT 40            // smem tile leading dim (32 + 8 pad)
#define WM_TILES 2
#define WN_TILES 4
// dynamic smem: tiles phase needs 2*128*40 = 10240 floats;
// epilogue staging needs 8 warps * 32*64 = 16384 floats.
#define GEMM_SMEM_FLOATS 16384
#define GEMM_SMEM_BYTES (GEMM_SMEM_FLOATS * 4)

// Shared GEMM mainloop: leaves per-warp 32x64 result staged in smem.
// Returns pointer to this warp's staging region (row-major, ld=64).
__device__ __forceinline__
float* gemm_mainloop_tf32(const float* __restrict__ Aptr,   // block A base [.., K]
                          const float* __restrict__ Bptr,   // block B base [.., K]
                          float* sm, int tid)
{
    float* As = sm;                 // [BM][LDT]
    float* Bs = sm + BM * LDT;      // [BN][LDT]

    const int warp_id = tid >> 5;
    const int lane    = tid & 31;
    const int wm = warp_id & 3;     // 0..3  (32-row slab)
    const int wn = warp_id >> 2;    // 0..1  (64-col slab)

    wmma::fragment<wmma::accumulator, 16, 16, 8, float> c[WM_TILES][WN_TILES];
    #pragma unroll
    for (int i = 0; i < WM_TILES; i++)
        #pragma unroll
        for (int j = 0; j < WN_TILES; j++)
            wmma::fill_fragment(c[i][j], 0.0f);

    const int loadRowBase = tid >> 3;        // 0..31
    const int loadCol     = (tid & 7) * 4;   // 0..28

    for (int k0 = 0; k0 < CH; k0 += BKO) {
        // Load 128x32 A and B tiles (4 passes of 32 rows, float4 each)
        #pragma unroll
        for (int p = 0; p < 4; p++) {
            const int row = p * 32 + loadRowBase;
            float4 va = *(const float4*)(Aptr + (size_t)row * CH + k0 + loadCol);
            *(float4*)(As + row * LDT + loadCol) = va;
            float4 vb = *(const float4*)(Bptr + (size_t)row * CH + k0 + loadCol);
            *(float4*)(Bs + row * LDT + loadCol) = vb;
        }
        __syncthreads();

        #pragma unroll
        for (int kk = 0; kk < BKO / 8; kk++) {
            wmma::fragment<wmma::matrix_a, 16, 16, 8, wmma::precision::tf32, wmma::row_major> a[WM_TILES];
            wmma::fragment<wmma::matrix_b, 16, 16, 8, wmma::precision::tf32, wmma::col_major> b[WN_TILES];
            #pragma unroll
            for (int i = 0; i < WM_TILES; i++) {
                const float* ap = As + (wm * 32 + i * 16) * LDT + kk * 8;
                wmma::load_matrix_sync(a[i], ap, LDT);
                #pragma unroll
                for (int t = 0; t < a[i].num_elements; t++)
                    a[i].x[t] = wmma::__float_to_tf32(a[i].x[t]);
            }
            #pragma unroll
            for (int j = 0; j < WN_TILES; j++) {
                // col-major view of row-major [N][K] tile: elem(k,n) at n*LDT + k
                const float* bp = Bs + (wn * 64 + j * 16) * LDT + kk * 8;
                wmma::load_matrix_sync(b[j], bp, LDT);
                #pragma unroll
                for (int t = 0; t < b[j].num_elements; t++)
                    b[j].x[t] = wmma::__float_to_tf32(b[j].x[t]);
            }
            #pragma unroll
            for (int i = 0; i < WM_TILES; i++)
                #pragma unroll
                for (int j = 0; j < WN_TILES; j++)
                    wmma::mma_sync(c[i][j], a[i], b[j], c[i][j]);
        }
        __syncthreads();
    }

    // Stage result in smem (reuse tile memory): per-warp 32x64, ld=64
    float* Cs = sm + warp_id * 32 * 64;
    #pragma unroll
    for (int i = 0; i < WM_TILES; i++)
        #pragma unroll
        for (int j = 0; j < WN_TILES; j++)
            wmma::store_matrix_sync(Cs + i * 16 * 64 + j * 16, c[i][j], 64,
                                    wmma::mem_row_major);
    __syncwarp();
    (void)lane;
    return Cs;
}

// ---------------------------------------------------------------------------
// Kernel 1: fused QKV projection (TF32 tensor cores)
// ---------------------------------------------------------------------------
__global__ __launch_bounds__(256)
void qkv_gemm_kernel(const float* __restrict__ X,   // [M_ROWS, CH]
                     const float* __restrict__ W,   // [THREE_C, CH]
                     const float* __restrict__ qb,  // [CH]
                     const float* __restrict__ vb)  // [CH]
{
    extern __shared__ float sm[];
    const int bn = blockIdx.x;
    const int bm = blockIdx.y;
    const int tid = threadIdx.x;

    float* Cs = gemm_mainloop_tf32(X + (size_t)(bm * BM) * CH,
                                   W + (size_t)(bn * BN) * CH, sm, tid);

    const int warp_id = tid >> 5;
    const int lane    = tid & 31;
    const int wm = warp_id & 3;
    const int wn = warp_id >> 2;

    const int jblock = bn * BN;          // 128 cols, entirely within q, k, or v
    const int which  = jblock / CH;      // 0=q 1=k 2=v (128 | 768)

    for (int e = lane; e < 32 * 64; e += 32) {
        const int row = e >> 6;
        const int col = e & 63;
        const int i = bm * BM + wm * 32 + row;
        const int j = jblock + wn * 64 + col;
        const int cbase = j - which * CH;
        const int h = cbase >> 6;
        const int d = cbase & 63;
        const int b = i / SEQ;
        const int n = i % SEQ;
        const size_t base = (((size_t)(b * NH + h)) * SEQ + n) * HD + d;
        const float acc = Cs[e];
        if (which == 0)      g_q[base] = (acc + qb[cbase]) * SCALE;
        else if (which == 1) g_k[base] = acc;
        else                 g_v[base] = acc + vb[cbase];
    }
}

// ---------------------------------------------------------------------------
// Kernel 2: rpb gather  rpb[h,i,j] = table[rel_index[i,j], h]
// ---------------------------------------------------------------------------
__global__ void rpb_gather_kernel(const float* __restrict__ table, // [729, NH]
                                  const int* __restrict__ relidx)  // [SEQ*SEQ]
{
    int idx = blockIdx.x * blockDim.x + threadIdx.x;
    const int total = NH * SEQ * SEQ;
    if (idx >= total) return;
    int ij = idx % (SEQ * SEQ);
    int h  = idx / (SEQ * SEQ);
    g_rpb[idx] = table[relidx[ij] * NH + h];
}

// ---------------------------------------------------------------------------
// Kernel 3: attention per (b,h). K,V in smem; one thread per query row.
// ---------------------------------------------------------------------------
__global__ __launch_bounds__(224, 1)
void attn_kernel()
{
    extern __shared__ float smem[];
    float* Ks = smem;                 // [SEQ][HD]
    float* Vs = smem + SEQ * HD;      // [SEQ][HD]

    const int bh = blockIdx.x;
    const int b = bh / NH;
    const int h = bh % NH;
    const int tid = threadIdx.x;

    const float* Kg = g_k + (size_t)bh * SEQ * HD;
    const float* Vg = g_v + (size_t)bh * SEQ * HD;

    for (int t = tid; t < (SEQ * HD) / 4; t += 224) {
        ((float4*)Ks)[t] = ((const float4*)Kg)[t];
        ((float4*)Vs)[t] = ((const float4*)Vg)[t];
    }
    __syncthreads();

    if (tid >= SEQ) return;

    float qr[HD];
    const float* Qg = g_q + (size_t)bh * SEQ * HD + (size_t)tid * HD;
    #pragma unroll
    for (int d = 0; d < HD; d += 4) {
        float4 v = *(const float4*)(Qg + d);
        qr[d] = v.x; qr[d+1] = v.y; qr[d+2] = v.z; qr[d+3] = v.w;
    }

    const float* rpb = g_rpb + (size_t)h * SEQ * SEQ + (size_t)tid * SEQ;

    float s[SEQ];
    float mx = -1e30f;
    for (int j = 0; j < SEQ; j++) {
        const float* kj = Ks + j * HD;
        float a = rpb[j];
        #pragma unroll
        for (int d = 0; d < HD; d++) a = fmaf(qr[d], kj[d], a);
        s[j] = a;
        mx = fmaxf(mx, a);
    }

    float o[HD];
    #pragma unroll
    for (int d = 0; d < HD; d++) o[d] = 0.f;
    float l = 0.f;
    for (int j = 0; j < SEQ; j++) {
        float p = __expf(s[j] - mx);
        l += p;
        const float* vj = Vs + j * HD;
        #pragma unroll
        for (int d = 0; d < HD; d++) o[d] = fmaf(p, vj[d], o[d]);
    }
    const float inv = 1.f / l;

    float* outp = g_att + ((size_t)(b * SEQ + tid)) * CH + h * HD;
    #pragma unroll
    for (int d = 0; d < HD; d += 4) {
        float4 v;
        v.x = o[d] * inv; v.y = o[d+1] * inv;
        v.z = o[d+2] * inv; v.w = o[d+3] * inv;
        *(float4*)(outp + d) = v;
    }
}

// ---------------------------------------------------------------------------
// Kernel 4: output projection (TF32 tensor cores)
// ---------------------------------------------------------------------------
__global__ __launch_bounds__(256)
void proj_gemm_kernel(const float* __restrict__ W,   // [CH, CH]
                      const float* __restrict__ pb,  // [CH]
                      float* __restrict__ out)       // [M_ROWS, CH]
{
    extern __shared__ float sm[];
    const int bn = blockIdx.x;
    const int bm = blockIdx.y;
    const int tid = threadIdx.x;

    float* Cs = gemm_mainloop_tf32(g_att + (size_t)(bm * BM) * CH,
                                   W + (size_t)(bn * BN) * CH, sm, tid);

    const int warp_id = tid >> 5;
    const int lane    = tid & 31;
    const int wm = warp_id & 3;
    const int wn = warp_id >> 2;

    for (int e = lane; e < 32 * 64; e += 32) {
        const int row = e >> 6;
        const int col = e & 63;
        const int i = bm * BM + wm * 32 + row;
        const int j = bn * BN + wn * 64 + col;
        out[(size_t)i * CH + j] = Cs[e] + pb[j];
    }
}

// ---------------------------------------------------------------------------
// Launch
// ---------------------------------------------------------------------------
extern "C" void kernel_launch(void* const* d_in, const int* in_sizes, int n_in,
                              void* d_out, int out_size)
{
    const float* x       = (const float*)d_in[0];
    const float* qkv_w   = (const float*)d_in[1];
    const float* q_bias  = (const float*)d_in[2];
    const float* v_bias  = (const float*)d_in[3];
    const float* rpb_tab = (const float*)d_in[4];
    const float* proj_w  = (const float*)d_in[5];
    const float* proj_b  = (const float*)d_in[6];
    const int*   relidx  = (const int*)d_in[7];
    float*       out     = (float*)d_out;

    static bool attrs_set = false;
    if (!attrs_set) {
        cudaFuncSetAttribute(qkv_gemm_kernel,
                             cudaFuncAttributeMaxDynamicSharedMemorySize,
                             GEMM_SMEM_BYTES);
        cudaFuncSetAttribute(proj_gemm_kernel,
                             cudaFuncAttributeMaxDynamicSharedMemorySize,
                             GEMM_SMEM_BYTES);
        cudaFuncSetAttribute(attn_kernel,
                             cudaFuncAttributeMaxDynamicSharedMemorySize,
                             2 * SEQ * HD * sizeof(float));
        attrs_set = true;
    }

    // 1. QKV projection (TF32)
    {
        dim3 grid(THREE_C / BN, M_ROWS / BM);
        qkv_gemm_kernel<<<grid, 256, GEMM_SMEM_BYTES>>>(x, qkv_w, q_bias, v_bias);
    }
    // 2. RPB gather
    {
        const int total = NH * SEQ * SEQ;
        rpb_gather_kernel<<<(total + 255) / 256, 256>>>(rpb_tab, relidx);
    }
    // 3. Attention
    {
        const int smem_bytes = 2 * SEQ * HD * sizeof(float);
        attn_kernel<<<BATCH * NH, 224, smem_bytes>>>();
    }
    // 4. Projection (TF32)
    {
        dim3 grid(CH / BN, M_ROWS / BM);
        proj_gemm_kernel<<<grid, 256, GEMM_SMEM_BYTES>>>(proj_w, proj_b, out);
    }
}

// round 3
// speedup vs baseline: 2.4334x; 2.0882x over previous
#include <cuda_runtime.h>
#include <cuda_bf16.h>

// Problem constants
#define BATCH 256
#define SEQ   196
#define CH    768
#define NH    12
#define HD    64
#define M_ROWS (BATCH * SEQ)       // 50176
#define THREE_C (3 * CH)           // 2304
#define SCALE 0.125f

// Scratch
__device__ float g_q[(size_t)BATCH * NH * SEQ * HD];   // [B,H,N,hd]
__device__ float g_k[(size_t)BATCH * NH * SEQ * HD];
__device__ float g_v[(size_t)BATCH * NH * SEQ * HD];
__device__ float g_rpb[(size_t)NH * SEQ * SEQ];        // [H,N,N]
__device__ float g_att[(size_t)M_ROWS * CH];           // [B,N,C] pre-proj

// ---------------------------------------------------------------------------
// TF32 mma.sync GEMM: C[M,N] = A[M,K] @ B[N,K]^T, K = CH = 768
// 128x128x32 block tile, 256 threads, 2-stage cp.async pipeline.
// Warp tile 64x32: 4 m-frags x 4 n-frags of m16n8k8.
// ---------------------------------------------------------------------------
#define BM 128
#define BN 128
#define BK 32
#define SMEM_STAGE_FLOATS (BM * BK + BN * BK)    // 8192
#define GEMM_SMEM_BYTES (2 * SMEM_STAGE_FLOATS * 4)  // 65536

__device__ __forceinline__ void cp_async16(float* smem_ptr, const float* gmem_ptr) {
    unsigned saddr = (unsigned)__cvta_generic_to_shared(smem_ptr);
    asm volatile("cp.async.cg.shared.global [%0], [%1], 16;\n"
                 :: "r"(saddr), "l"(gmem_ptr));
}
__device__ __forceinline__ void cp_commit() {
    asm volatile("cp.async.commit_group;\n");
}
template <int N>
__device__ __forceinline__ void cp_wait() {
    asm volatile("cp.async.wait_group %0;\n" :: "n"(N));
}
__device__ __forceinline__ unsigned f2tf32(float x) {
    unsigned r;
    asm("cvt.rna.tf32.f32 %0, %1;\n" : "=r"(r) : "f"(x));
    return r;
}
__device__ __forceinline__ void mma_tf32(float c[4], unsigned a0, unsigned a1,
                                         unsigned a2, unsigned a3,
                                         unsigned b0, unsigned b1) {
    asm volatile(
        "mma.sync.aligned.m16n8k8.row.col.f32.tf32.tf32.f32 "
        "{%0,%1,%2,%3}, {%4,%5,%6,%7}, {%8,%9}, {%0,%1,%2,%3};\n"
        : "+f"(c[0]), "+f"(c[1]), "+f"(c[2]), "+f"(c[3])
        : "r"(a0), "r"(a1), "r"(a2), "r"(a3), "r"(b0), "r"(b1));
}

// Shared mainloop: fills acc[mi][ni][4].
__device__ __forceinline__
void gemm_mainloop(const float* __restrict__ Aptr,  // block base, ld=CH
                   const float* __restrict__ Bptr,  // block base, ld=CH
                   float* sm, int tid, float acc[4][4][4])
{
    const int warp = tid >> 5;
    const int lane = tid & 31;
    const int g  = lane >> 2;      // 0..7
    const int tg = lane & 3;       // 0..3
    const int wr = warp & 1;       // row slab (64)
    const int wc = warp >> 1;      // col slab (32)

    const int ldr = tid >> 3;      // 0..31 load row within pass
    const int ldc = tid & 7;       // 0..7 chunk

    #pragma unroll
    for (int i = 0; i < 4; i++)
        #pragma unroll
        for (int j = 0; j < 4; j++)
            #pragma unroll
            for (int t = 0; t < 4; t++) acc[i][j][t] = 0.f;

    // prefetch lambda
    auto prefetch = [&](int stage, int k0) {
        float* As = sm + stage * SMEM_STAGE_FLOATS;
        float* Bs = As + BM * BK;
        #pragma unroll
        for (int p = 0; p < 4; p++) {
            const int row = p * 32 + ldr;
            const int sc = (ldc ^ (row & 7)) << 2;
            cp_async16(As + row * BK + sc, Aptr + (size_t)row * CH + k0 + ldc * 4);
            cp_async16(Bs + row * BK + sc, Bptr + (size_t)row * CH + k0 + ldc * 4);
        }
    };

    prefetch(0, 0);
    cp_commit();

    const int NKT = CH / BK;   // 24
    #pragma unroll 1
    for (int kt = 0; kt < NKT; kt++) {
        if (kt + 1 < NKT) { prefetch((kt + 1) & 1, (kt + 1) * BK); cp_commit(); }
        if (kt + 1 < NKT) cp_wait<1>(); else cp_wait<0>();
        __syncthreads();

        const float* As = sm + (kt & 1) * SMEM_STAGE_FLOATS;
        const float* Bs = As + BM * BK;

        #pragma unroll
        for (int ks = 0; ks < 4; ks++) {
            const int ca = 2 * ks;
            const int c0 = ((ca ^ g) << 2) + tg;       // swizzled col for k0..k0+3
            const int c1 = (((ca + 1) ^ g) << 2) + tg; // for k0+4..k0+7
            unsigned a[4][4], b[4][2];
            #pragma unroll
            for (int mi = 0; mi < 4; mi++) {
                const int r = wr * 64 + mi * 16 + g;
                const float* p0 = As + r * BK;
                const float* p1 = As + (r + 8) * BK;
                a[mi][0] = f2tf32(p0[c0]);
                a[mi][1] = f2tf32(p1[c0]);
                a[mi][2] = f2tf32(p0[c1]);
                a[mi][3] = f2tf32(p1[c1]);
            }
            #pragma unroll
            for (int ni = 0; ni < 4; ni++) {
                const int n = wc * 32 + ni * 8 + g;
                const float* pn = Bs + n * BK;
                b[ni][0] = f2tf32(pn[c0]);
                b[ni][1] = f2tf32(pn[c1]);
            }
            #pragma unroll
            for (int mi = 0; mi < 4; mi++)
                #pragma unroll
                for (int ni = 0; ni < 4; ni++)
                    mma_tf32(acc[mi][ni], a[mi][0], a[mi][1], a[mi][2], a[mi][3],
                             b[ni][0], b[ni][1]);
        }
        __syncthreads();
    }
}

// ---------------------------------------------------------------------------
// Kernel 1: fused QKV projection
// ---------------------------------------------------------------------------
__global__ __launch_bounds__(256, 2)
void qkv_gemm_kernel(const float* __restrict__ X,
                     const float* __restrict__ W,
                     const float* __restrict__ qb,
                     const float* __restrict__ vb)
{
    extern __shared__ float sm[];
    const int bn = blockIdx.x;
    const int bm = blockIdx.y;
    const int tid = threadIdx.x;

    float acc[4][4][4];
    gemm_mainloop(X + (size_t)(bm * BM) * CH, W + (size_t)(bn * BN) * CH,
                  sm, tid, acc);

    const int warp = tid >> 5;
    const int lane = tid & 31;
    const int g = lane >> 2, tg = lane & 3;
    const int wr = warp & 1, wc = warp >> 1;

    const int jblock = bn * BN;
    const int which = jblock / CH;   // uniform per block

    #pragma unroll
    for (int mi = 0; mi < 4; mi++) {
        #pragma unroll
        for (int ni = 0; ni < 4; ni++) {
            const int jl = wc * 32 + ni * 8 + tg * 2;
            const int cbase = jblock + jl - which * CH;
            const int h = cbase >> 6;
            const int d = cbase & 63;
            #pragma unroll
            for (int rr = 0; rr < 2; rr++) {
                const int i = bm * BM + wr * 64 + mi * 16 + g + rr * 8;
                const int b = i / SEQ;
                const int n = i - b * SEQ;
                const size_t base = (((size_t)(b * NH + h)) * SEQ + n) * HD + d;
                const float v0 = acc[mi][ni][rr * 2 + 0];
                const float v1 = acc[mi][ni][rr * 2 + 1];
                float2 out;
                if (which == 0) {
                    float2 qb2 = *(const float2*)(qb + cbase);
                    out.x = (v0 + qb2.x) * SCALE;
                    out.y = (v1 + qb2.y) * SCALE;
                    *(float2*)(g_q + base) = out;
                } else if (which == 1) {
                    out.x = v0; out.y = v1;
                    *(float2*)(g_k + base) = out;
                } else {
                    float2 vb2 = *(const float2*)(vb + cbase);
                    out.x = v0 + vb2.x;
                    out.y = v1 + vb2.y;
                    *(float2*)(g_v + base) = out;
                }
            }
        }
    }
}

// ---------------------------------------------------------------------------
// Kernel 2: rpb gather
// ---------------------------------------------------------------------------
__global__ void rpb_gather_kernel(const float* __restrict__ table,
                                  const int* __restrict__ relidx)
{
    int idx = blockIdx.x * blockDim.x + threadIdx.x;
    const int total = NH * SEQ * SEQ;
    if (idx >= total) return;
    int ij = idx % (SEQ * SEQ);
    int h  = idx / (SEQ * SEQ);
    g_rpb[idx] = table[relidx[ij] * NH + h];
}

// ---------------------------------------------------------------------------
// Kernel 3: attention per (b,h) — chunked online softmax (no local spills)
// ---------------------------------------------------------------------------
#define CHUNK 28
__global__ __launch_bounds__(224, 1)
void attn_kernel()
{
    extern __shared__ float smem[];
    float* Ks = smem;                 // [SEQ][HD]
    float* Vs = smem + SEQ * HD;      // [SEQ][HD]

    const int bh = blockIdx.x;
    const int b = bh / NH;
    const int h = bh % NH;
    const int tid = threadIdx.x;

    const float* Kg = g_k + (size_t)bh * SEQ * HD;
    const float* Vg = g_v + (size_t)bh * SEQ * HD;

    for (int t = tid; t < (SEQ * HD) / 4; t += 224) {
        ((float4*)Ks)[t] = ((const float4*)Kg)[t];
        ((float4*)Vs)[t] = ((const float4*)Vg)[t];
    }
    __syncthreads();

    if (tid >= SEQ) return;

    float qr[HD];
    const float* Qg = g_q + (size_t)bh * SEQ * HD + (size_t)tid * HD;
    #pragma unroll
    for (int d = 0; d < HD; d += 4) {
        float4 v = *(const float4*)(Qg + d);
        qr[d] = v.x; qr[d+1] = v.y; qr[d+2] = v.z; qr[d+3] = v.w;
    }

    const float* rpb = g_rpb + (size_t)h * SEQ * SEQ + (size_t)tid * SEQ;

    float o[HD];
    #pragma unroll
    for (int d = 0; d < HD; d++) o[d] = 0.f;
    float l = 0.f;
    float mx = -1e30f;

    #pragma unroll 1
    for (int c0 = 0; c0 < SEQ; c0 += CHUNK) {
        float s[CHUNK];
        float cm = -1e30f;
        #pragma unroll
        for (int jj = 0; jj < CHUNK; jj++) {
            const int j = c0 + jj;
            const float* kj = Ks + j * HD;
            float a = rpb[j];
            #pragma unroll
            for (int d = 0; d < HD; d++) a = fmaf(qr[d], kj[d], a);
            s[jj] = a;
            cm = fmaxf(cm, a);
        }
        if (cm > mx) {
            const float corr = __expf(mx - cm);
            l *= corr;
            #pragma unroll
            for (int d = 0; d < HD; d++) o[d] *= corr;
            mx = cm;
        }
        #pragma unroll
        for (int jj = 0; jj < CHUNK; jj++) {
            const float p = __expf(s[jj] - mx);
            l += p;
            const float* vj = Vs + (c0 + jj) * HD;
            #pragma unroll
            for (int d = 0; d < HD; d++) o[d] = fmaf(p, vj[d], o[d]);
        }
    }
    const float inv = 1.f / l;

    float* outp = g_att + ((size_t)(b * SEQ + tid)) * CH + h * HD;
    #pragma unroll
    for (int d = 0; d < HD; d += 4) {
        float4 v;
        v.x = o[d] * inv; v.y = o[d+1] * inv;
        v.z = o[d+2] * inv; v.w = o[d+3] * inv;
        *(float4*)(outp + d) = v;
    }
}

// ---------------------------------------------------------------------------
// Kernel 4: output projection
// ---------------------------------------------------------------------------
__global__ __launch_bounds__(256, 2)
void proj_gemm_kernel(const float* __restrict__ W,
                      const float* __restrict__ pb,
                      float* __restrict__ out)
{
    extern __shared__ float sm[];
    const int bn = blockIdx.x;
    const int bm = blockIdx.y;
    const int tid = threadIdx.x;

    float acc[4][4][4];
    gemm_mainloop(g_att + (size_t)(bm * BM) * CH, W + (size_t)(bn * BN) * CH,
                  sm, tid, acc);

    const int warp = tid >> 5;
    const int lane = tid & 31;
    const int g = lane >> 2, tg = lane & 3;
    const int wr = warp & 1, wc = warp >> 1;

    #pragma unroll
    for (int mi = 0; mi < 4; mi++) {
        #pragma unroll
        for (int ni = 0; ni < 4; ni++) {
            const int j = bn * BN + wc * 32 + ni * 8 + tg * 2;
            const float2 pb2 = *(const float2*)(pb + j);
            #pragma unroll
            for (int rr = 0; rr < 2; rr++) {
                const int i = bm * BM + wr * 64 + mi * 16 + g + rr * 8;
                float2 o2;
                o2.x = acc[mi][ni][rr * 2 + 0] + pb2.x;
                o2.y = acc[mi][ni][rr * 2 + 1] + pb2.y;
                *(float2*)(out + (size_t)i * CH + j) = o2;
            }
        }
    }
}

// ---------------------------------------------------------------------------
// Launch
// ---------------------------------------------------------------------------
extern "C" void kernel_launch(void* const* d_in, const int* in_sizes, int n_in,
                              void* d_out, int out_size)
{
    const float* x       = (const float*)d_in[0];
    const float* qkv_w   = (const float*)d_in[1];
    const float* q_bias  = (const float*)d_in[2];
    const float* v_bias  = (const float*)d_in[3];
    const float* rpb_tab = (const float*)d_in[4];
    const float* proj_w  = (const float*)d_in[5];
    const float* proj_b  = (const float*)d_in[6];
    const int*   relidx  = (const int*)d_in[7];
    float*       out     = (float*)d_out;

    static bool attrs_set = false;
    if (!attrs_set) {
        cudaFuncSetAttribute(qkv_gemm_kernel,
                             cudaFuncAttributeMaxDynamicSharedMemorySize,
                             GEMM_SMEM_BYTES);
        cudaFuncSetAttribute(proj_gemm_kernel,
                             cudaFuncAttributeMaxDynamicSharedMemorySize,
                             GEMM_SMEM_BYTES);
        cudaFuncSetAttribute(attn_kernel,
                             cudaFuncAttributeMaxDynamicSharedMemorySize,
                             2 * SEQ * HD * sizeof(float));
        attrs_set = true;
    }

    // 1. QKV projection (TF32 mma)
    {
        dim3 grid(THREE_C / BN, M_ROWS / BM);
        qkv_gemm_kernel<<<grid, 256, GEMM_SMEM_BYTES>>>(x, qkv_w, q_bias, v_bias);
    }
    // 2. RPB gather
    {
        const int total = NH * SEQ * SEQ;
        rpb_gather_kernel<<<(total + 255) / 256, 256>>>(rpb_tab, relidx);
    }
    // 3. Attention
    {
        const int smem_bytes = 2 * SEQ * HD * sizeof(float);
        attn_kernel<<<BATCH * NH, 224, smem_bytes>>>();
    }
    // 4. Projection (TF32 mma)
    {
        dim3 grid(CH / BN, M_ROWS / BM);
        proj_gemm_kernel<<<grid, 256, GEMM_SMEM_BYTES>>>(proj_w, proj_b, out);
    }
}

// round 4
// speedup vs baseline: 3.1036x; 1.2755x over previous
#include <cuda_runtime.h>
#include <cuda_bf16.h>

// Problem constants
#define BATCH 256
#define SEQ   196
#define CH    768
#define NH    12
#define HD    64
#define M_ROWS (BATCH * SEQ)       // 50176
#define THREE_C (3 * CH)           // 2304
#define SCALE 0.125f

// Scratch
__device__ float g_q[(size_t)BATCH * NH * SEQ * HD];   // [B,H,N,hd] (TF32-rounded)
__device__ float g_k[(size_t)BATCH * NH * SEQ * HD];
__device__ float g_v[(size_t)BATCH * NH * SEQ * HD];
__device__ float g_rpb[(size_t)NH * SEQ * SEQ];        // [H,N,N]
__device__ float g_att[(size_t)M_ROWS * CH];           // [B,N,C] (TF32-rounded)
__device__ float g_xr[(size_t)M_ROWS * CH];            // TF32-rounded x
__device__ float g_wr[(size_t)THREE_C * CH];           // TF32-rounded qkv_w
__device__ float g_pwr[(size_t)CH * CH];               // TF32-rounded proj_w

// ---------------------------------------------------------------------------
// PTX helpers
// ---------------------------------------------------------------------------
__device__ __forceinline__ void cp_async16(float* smem_ptr, const float* gmem_ptr) {
    unsigned saddr = (unsigned)__cvta_generic_to_shared(smem_ptr);
    asm volatile("cp.async.cg.shared.global [%0], [%1], 16;\n"
                 :: "r"(saddr), "l"(gmem_ptr));
}
__device__ __forceinline__ void cp_commit() {
    asm volatile("cp.async.commit_group;\n");
}
template <int N>
__device__ __forceinline__ void cp_wait() {
    asm volatile("cp.async.wait_group %0;\n" :: "n"(N));
}
__device__ __forceinline__ unsigned f2tf32(float x) {
    unsigned r;
    asm("cvt.rna.tf32.f32 %0, %1;\n" : "=r"(r) : "f"(x));
    return r;
}
__device__ __forceinline__ float tf32_round(float x) {
    return __uint_as_float(f2tf32(x));
}
__device__ __forceinline__ void mma_tf32(float c[4], unsigned a0, unsigned a1,
                                         unsigned a2, unsigned a3,
                                         unsigned b0, unsigned b1) {
    asm volatile(
        "mma.sync.aligned.m16n8k8.row.col.f32.tf32.tf32.f32 "
        "{%0,%1,%2,%3}, {%4,%5,%6,%7}, {%8,%9}, {%0,%1,%2,%3};\n"
        : "+f"(c[0]), "+f"(c[1]), "+f"(c[2]), "+f"(c[3])
        : "r"(a0), "r"(a1), "r"(a2), "r"(a3), "r"(b0), "r"(b1));
}

// ---------------------------------------------------------------------------
// Kernel 0: elementwise TF32 rounding (inputs pre-rounded so GEMMs skip cvt)
// ---------------------------------------------------------------------------
__global__ void round_tf32_kernel(const float* __restrict__ src,
                                  float* __restrict__ dst, int n4)
{
    int i = blockIdx.x * blockDim.x + threadIdx.x;
    if (i >= n4) return;
    float4 v = ((const float4*)src)[i];
    v.x = tf32_round(v.x); v.y = tf32_round(v.y);
    v.z = tf32_round(v.z); v.w = tf32_round(v.w);
    ((float4*)dst)[i] = v;
}

// ---------------------------------------------------------------------------
// TF32 mma GEMM mainloop (inputs already TF32-exact -> no cvt in loop)
// ---------------------------------------------------------------------------
#define BM 128
#define BN 128
#define BK 32
#define SMEM_STAGE_FLOATS (BM * BK + BN * BK)
#define GEMM_SMEM_BYTES (2 * SMEM_STAGE_FLOATS * 4)

__device__ __forceinline__
void gemm_mainloop(const float* __restrict__ Aptr,
                   const float* __restrict__ Bptr,
                   float* sm, int tid, float acc[4][4][4])
{
    const int warp = tid >> 5;
    const int lane = tid & 31;
    const int g  = lane >> 2;
    const int tg = lane & 3;
    const int wr = warp & 1;
    const int wc = warp >> 1;

    const int ldr = tid >> 3;
    const int ldc = tid & 7;

    #pragma unroll
    for (int i = 0; i < 4; i++)
        #pragma unroll
        for (int j = 0; j < 4; j++)
            #pragma unroll
            for (int t = 0; t < 4; t++) acc[i][j][t] = 0.f;

    auto prefetch = [&](int stage, int k0) {
        float* As = sm + stage * SMEM_STAGE_FLOATS;
        float* Bs = As + BM * BK;
        #pragma unroll
        for (int p = 0; p < 4; p++) {
            const int row = p * 32 + ldr;
            const int sc = (ldc ^ (row & 7)) << 2;
            cp_async16(As + row * BK + sc, Aptr + (size_t)row * CH + k0 + ldc * 4);
            cp_async16(Bs + row * BK + sc, Bptr + (size_t)row * CH + k0 + ldc * 4);
        }
    };

    prefetch(0, 0);
    cp_commit();

    const int NKT = CH / BK;
    #pragma unroll 1
    for (int kt = 0; kt < NKT; kt++) {
        if (kt + 1 < NKT) { prefetch((kt + 1) & 1, (kt + 1) * BK); cp_commit(); }
        if (kt + 1 < NKT) cp_wait<1>(); else cp_wait<0>();
        __syncthreads();

        const float* As = sm + (kt & 1) * SMEM_STAGE_FLOATS;
        const float* Bs = As + BM * BK;

        #pragma unroll
        for (int ks = 0; ks < 4; ks++) {
            const int ca = 2 * ks;
            const int c0 = ((ca ^ g) << 2) + tg;
            const int c1 = (((ca + 1) ^ g) << 2) + tg;
            unsigned a[4][4], b[4][2];
            #pragma unroll
            for (int mi = 0; mi < 4; mi++) {
                const int r = wr * 64 + mi * 16 + g;
                const float* p0 = As + r * BK;
                const float* p1 = As + (r + 8) * BK;
                a[mi][0] = __float_as_uint(p0[c0]);
                a[mi][1] = __float_as_uint(p1[c0]);
                a[mi][2] = __float_as_uint(p0[c1]);
                a[mi][3] = __float_as_uint(p1[c1]);
            }
            #pragma unroll
            for (int ni = 0; ni < 4; ni++) {
                const int n = wc * 32 + ni * 8 + g;
                const float* pn = Bs + n * BK;
                b[ni][0] = __float_as_uint(pn[c0]);
                b[ni][1] = __float_as_uint(pn[c1]);
            }
            #pragma unroll
            for (int mi = 0; mi < 4; mi++)
                #pragma unroll
                for (int ni = 0; ni < 4; ni++)
                    mma_tf32(acc[mi][ni], a[mi][0], a[mi][1], a[mi][2], a[mi][3],
                             b[ni][0], b[ni][1]);
        }
        __syncthreads();
    }
}

// ---------------------------------------------------------------------------
// Kernel 1: fused QKV projection; outputs TF32-rounded q/k/v in [B,H,N,hd]
// ---------------------------------------------------------------------------
__global__ __launch_bounds__(256, 2)
void qkv_gemm_kernel(const float* __restrict__ qb,
                     const float* __restrict__ vb)
{
    extern __shared__ float sm[];
    const int bn = blockIdx.x;
    const int bm = blockIdx.y;
    const int tid = threadIdx.x;

    float acc[4][4][4];
    gemm_mainloop(g_xr + (size_t)(bm * BM) * CH, g_wr + (size_t)(bn * BN) * CH,
                  sm, tid, acc);

    const int warp = tid >> 5;
    const int lane = tid & 31;
    const int g = lane >> 2, tg = lane & 3;
    const int wr = warp & 1, wc = warp >> 1;

    const int jblock = bn * BN;
    const int which = jblock / CH;

    #pragma unroll
    for (int mi = 0; mi < 4; mi++) {
        #pragma unroll
        for (int ni = 0; ni < 4; ni++) {
            const int jl = wc * 32 + ni * 8 + tg * 2;
            const int cbase = jblock + jl - which * CH;
            const int h = cbase >> 6;
            const int d = cbase & 63;
            #pragma unroll
            for (int rr = 0; rr < 2; rr++) {
                const int i = bm * BM + wr * 64 + mi * 16 + g + rr * 8;
                const int b = i / SEQ;
                const int n = i - b * SEQ;
                const size_t base = (((size_t)(b * NH + h)) * SEQ + n) * HD + d;
                const float v0 = acc[mi][ni][rr * 2 + 0];
                const float v1 = acc[mi][ni][rr * 2 + 1];
                float2 out;
                if (which == 0) {
                    float2 qb2 = *(const float2*)(qb + cbase);
                    out.x = tf32_round((v0 + qb2.x) * SCALE);
                    out.y = tf32_round((v1 + qb2.y) * SCALE);
                    *(float2*)(g_q + base) = out;
                } else if (which == 1) {
                    out.x = tf32_round(v0); out.y = tf32_round(v1);
                    *(float2*)(g_k + base) = out;
                } else {
                    float2 vb2 = *(const float2*)(vb + cbase);
                    out.x = tf32_round(v0 + vb2.x);
                    out.y = tf32_round(v1 + vb2.y);
                    *(float2*)(g_v + base) = out;
                }
            }
        }
    }
}

// ---------------------------------------------------------------------------
// Kernel 2: rpb gather
// ---------------------------------------------------------------------------
__global__ void rpb_gather_kernel(const float* __restrict__ table,
                                  const int* __restrict__ relidx)
{
    int idx = blockIdx.x * blockDim.x + threadIdx.x;
    const int total = NH * SEQ * SEQ;
    if (idx >= total) return;
    int ij = idx % (SEQ * SEQ);
    int h  = idx / (SEQ * SEQ);
    g_rpb[idx] = table[relidx[ij] * NH + h];
}

// ---------------------------------------------------------------------------
// Kernel 3: TF32 mma attention. CTA = (b*NH+h, mtile). 256 threads = 8 warps,
// each warp owns a 16-query strip through both S=Q@K^T and O=P@V.
// N padded 196->200 (25 n8-tiles). Q rows padded to 128.
// ---------------------------------------------------------------------------
#define AT_LDQ 68
#define AT_LDK 68
#define AT_LDV 72
#define AT_LDP 200
#define AT_K_OFF 25600          // P region = [128][200] floats
#define AT_V_OFF (AT_K_OFF + 200 * AT_LDK)
#define AT_SMEM_FLOATS (AT_V_OFF + 200 * AT_LDV)   // 53600
#define AT_SMEM_BYTES (AT_SMEM_FLOATS * 4)          // 214400

__global__ __launch_bounds__(256, 1)
void attn_mma_kernel()
{
    extern __shared__ float sm[];
    float* P = sm;               // [128][AT_LDP]   (Q overlays first 8704 floats)
    float* Qs = sm;              // [128][AT_LDQ]
    float* Ks = sm + AT_K_OFF;   // [200][AT_LDK]
    float* Vs = sm + AT_V_OFF;   // [200][AT_LDV]

    const int bh = blockIdx.x;
    const int mt = blockIdx.y;          // 0: rows 0..127, 1: rows 128..195
    const int b = bh / NH;
    const int h = bh % NH;
    const int tid = threadIdx.x;
    const int warp = tid >> 5;
    const int lane = tid & 31;
    const int g = lane >> 2;
    const int tg = lane & 3;

    const float* Qg = g_q + (size_t)bh * SEQ * HD;
    const float* Kg = g_k + (size_t)bh * SEQ * HD;
    const float* Vg = g_v + (size_t)bh * SEQ * HD;

    const float4 z4 = make_float4(0.f, 0.f, 0.f, 0.f);

    // stage K [196][64] -> [200][68] (zero rows 196..199)
    for (int t = tid; t < 200 * 16; t += 256) {
        const int r = t >> 4, c = (t & 15) << 2;
        float4 v = (r < SEQ) ? *(const float4*)(Kg + r * HD + c) : z4;
        *(float4*)(Ks + r * AT_LDK + c) = v;
    }
    // stage V -> [200][72]
    for (int t = tid; t < 200 * 16; t += 256) {
        const int r = t >> 4, c = (t & 15) << 2;
        float4 v = (r < SEQ) ? *(const float4*)(Vg + r * HD + c) : z4;
        *(float4*)(Vs + r * AT_LDV + c) = v;
    }
    // stage Q tile -> [128][68] (zero padded rows)
    const int qbase = mt * 128;
    const int qrows = mt ? (SEQ - 128) : 128;
    for (int t = tid; t < 128 * 16; t += 256) {
        const int r = t >> 4, c = (t & 15) << 2;
        float4 v = (r < qrows) ? *(const float4*)(Qg + (qbase + r) * HD + c) : z4;
        *(float4*)(Qs + r * AT_LDQ + c) = v;
    }
    __syncthreads();

    // ---- Phase 1: S = Q @ K^T  (per warp: 16 x 200) ----
    const int r0 = warp * 16;
    float acc[25][4];
    #pragma unroll
    for (int t = 0; t < 25; t++)
        #pragma unroll
        for (int e = 0; e < 4; e++) acc[t][e] = 0.f;

    #pragma unroll
    for (int ks = 0; ks < 8; ks++) {
        const int k0 = ks * 8;
        const unsigned a0 = __float_as_uint(Qs[(r0 + g) * AT_LDQ + k0 + tg]);
        const unsigned a1 = __float_as_uint(Qs[(r0 + g + 8) * AT_LDQ + k0 + tg]);
        const unsigned a2 = __float_as_uint(Qs[(r0 + g) * AT_LDQ + k0 + tg + 4]);
        const unsigned a3 = __float_as_uint(Qs[(r0 + g + 8) * AT_LDQ + k0 + tg + 4]);
        #pragma unroll
        for (int t = 0; t < 25; t++) {
            const unsigned b0 = __float_as_uint(Ks[(t * 8 + g) * AT_LDK + k0 + tg]);
            const unsigned b1 = __float_as_uint(Ks[(t * 8 + g) * AT_LDK + k0 + tg + 4]);
            mma_tf32(acc[t], a0, a1, a2, a3, b0, b1);
        }
    }
    __syncthreads();   // all Q/K smem reads done (P overlays Q)

    // ---- rpb add + masking ----
    const int rlo = qbase + r0 + g;
    const int rhi = rlo + 8;
    const float* rp_lo = g_rpb + (size_t)h * SEQ * SEQ + (size_t)min(rlo, SEQ - 1) * SEQ;
    const float* rp_hi = g_rpb + (size_t)h * SEQ * SEQ + (size_t)min(rhi, SEQ - 1) * SEQ;
    #pragma unroll
    for (int t = 0; t < 25; t++) {
        const int c0 = t * 8 + 2 * tg;
        const int c1 = c0 + 1;
        if (c0 < SEQ) { acc[t][0] += __ldg(rp_lo + c0); acc[t][2] += __ldg(rp_hi + c0); }
        else          { acc[t][0] = -1e30f;             acc[t][2] = -1e30f; }
        if (c1 < SEQ) { acc[t][1] += __ldg(rp_lo + c1); acc[t][3] += __ldg(rp_hi + c1); }
        else          { acc[t][1] = -1e30f;             acc[t][3] = -1e30f; }
    }

    // ---- softmax (rows rlo, rhi) ----
    float mlo = -1e30f, mhi = -1e30f;
    #pragma unroll
    for (int t = 0; t < 25; t++) {
        mlo = fmaxf(mlo, fmaxf(acc[t][0], acc[t][1]));
        mhi = fmaxf(mhi, fmaxf(acc[t][2], acc[t][3]));
    }
    mlo = fmaxf(mlo, __shfl_xor_sync(0xffffffffu, mlo, 1));
    mlo = fmaxf(mlo, __shfl_xor_sync(0xffffffffu, mlo, 2));
    mhi = fmaxf(mhi, __shfl_xor_sync(0xffffffffu, mhi, 1));
    mhi = fmaxf(mhi, __shfl_xor_sync(0xffffffffu, mhi, 2));

    float llo = 0.f, lhi = 0.f;
    float* Prow_lo = P + (r0 + g) * AT_LDP;
    float* Prow_hi = P + (r0 + g + 8) * AT_LDP;
    #pragma unroll
    for (int t = 0; t < 25; t++) {
        const int c0 = t * 8 + 2 * tg;
        const float p0 = tf32_round(__expf(acc[t][0] - mlo));
        const float p1 = tf32_round(__expf(acc[t][1] - mlo));
        const float p2 = tf32_round(__expf(acc[t][2] - mhi));
        const float p3 = tf32_round(__expf(acc[t][3] - mhi));
        llo += p0 + p1;
        lhi += p2 + p3;
        Prow_lo[c0] = p0; Prow_lo[c0 + 1] = p1;
        Prow_hi[c0] = p2; Prow_hi[c0 + 1] = p3;
    }
    llo += __shfl_xor_sync(0xffffffffu, llo, 1);
    llo += __shfl_xor_sync(0xffffffffu, llo, 2);
    lhi += __shfl_xor_sync(0xffffffffu, lhi, 1);
    lhi += __shfl_xor_sync(0xffffffffu, lhi, 2);
    const float inv_lo = 1.f / llo;
    const float inv_hi = 1.f / lhi;

    __syncwarp();   // warp's own P rows complete (only own rows are read back)

    // ---- Phase 2: O = P @ V  (per warp: 16 x 64, K = 200) ----
    float oacc[8][4];
    #pragma unroll
    for (int nt = 0; nt < 8; nt++)
        #pragma unroll
        for (int e = 0; e < 4; e++) oacc[nt][e] = 0.f;

    #pragma unroll
    for (int kt = 0; kt < 25; kt++) {
        const int k0 = kt * 8;
        const unsigned a0 = __float_as_uint(Prow_lo[k0 + tg]);
        const unsigned a1 = __float_as_uint(Prow_hi[k0 + tg]);
        const unsigned a2 = __float_as_uint(Prow_lo[k0 + tg + 4]);
        const unsigned a3 = __float_as_uint(Prow_hi[k0 + tg + 4]);
        #pragma unroll
        for (int nt = 0; nt < 8; nt++) {
            const unsigned b0 = __float_as_uint(Vs[(k0 + tg) * AT_LDV + nt * 8 + g]);
            const unsigned b1 = __float_as_uint(Vs[(k0 + tg + 4) * AT_LDV + nt * 8 + g]);
            mma_tf32(oacc[nt], a0, a1, a2, a3, b0, b1);
        }
    }

    // ---- store O (TF32-rounded for the proj GEMM) ----
    #pragma unroll
    for (int nt = 0; nt < 8; nt++) {
        const int c = nt * 8 + 2 * tg;
        if (rlo < SEQ) {
            float2 o2;
            o2.x = tf32_round(oacc[nt][0] * inv_lo);
            o2.y = tf32_round(oacc[nt][1] * inv_lo);
            *(float2*)(g_att + ((size_t)(b * SEQ + rlo)) * CH + h * HD + c) = o2;
        }
        if (rhi < SEQ) {
            float2 o2;
            o2.x = tf32_round(oacc[nt][2] * inv_hi);
            o2.y = tf32_round(oacc[nt][3] * inv_hi);
            *(float2*)(g_att + ((size_t)(b * SEQ + rhi)) * CH + h * HD + c) = o2;
        }
    }
}

// ---------------------------------------------------------------------------
// Kernel 4: output projection
// ---------------------------------------------------------------------------
__global__ __launch_bounds__(256, 2)
void proj_gemm_kernel(const float* __restrict__ pb,
                      float* __restrict__ out)
{
    extern __shared__ float sm[];
    const int bn = blockIdx.x;
    const int bm = blockIdx.y;
    const int tid = threadIdx.x;

    float acc[4][4][4];
    gemm_mainloop(g_att + (size_t)(bm * BM) * CH, g_pwr + (size_t)(bn * BN) * CH,
                  sm, tid, acc);

    const int warp = tid >> 5;
    const int lane = tid & 31;
    const int g = lane >> 2, tg = lane & 3;
    const int wr = warp & 1, wc = warp >> 1;

    #pragma unroll
    for (int mi = 0; mi < 4; mi++) {
        #pragma unroll
        for (int ni = 0; ni < 4; ni++) {
            const int j = bn * BN + wc * 32 + ni * 8 + tg * 2;
            const float2 pb2 = *(const float2*)(pb + j);
            #pragma unroll
            for (int rr = 0; rr < 2; rr++) {
                const int i = bm * BM + wr * 64 + mi * 16 + g + rr * 8;
                float2 o2;
                o2.x = acc[mi][ni][rr * 2 + 0] + pb2.x;
                o2.y = acc[mi][ni][rr * 2 + 1] + pb2.y;
                *(float2*)(out + (size_t)i * CH + j) = o2;
            }
        }
    }
}

// ---------------------------------------------------------------------------
// Launch
// ---------------------------------------------------------------------------
extern "C" void kernel_launch(void* const* d_in, const int* in_sizes, int n_in,
                              void* d_out, int out_size)
{
    const float* x       = (const float*)d_in[0];
    const float* qkv_w   = (const float*)d_in[1];
    const float* q_bias  = (const float*)d_in[2];
    const float* v_bias  = (const float*)d_in[3];
    const float* rpb_tab = (const float*)d_in[4];
    const float* proj_w  = (const float*)d_in[5];
    const float* proj_b  = (const float*)d_in[6];
    const int*   relidx  = (const int*)d_in[7];
    float*       out     = (float*)d_out;

    static bool attrs_set = false;
    if (!attrs_set) {
        cudaFuncSetAttribute(qkv_gemm_kernel,
                             cudaFuncAttributeMaxDynamicSharedMemorySize,
                             GEMM_SMEM_BYTES);
        cudaFuncSetAttribute(proj_gemm_kernel,
                             cudaFuncAttributeMaxDynamicSharedMemorySize,
                             GEMM_SMEM_BYTES);
        cudaFuncSetAttribute(attn_mma_kernel,
                             cudaFuncAttributeMaxDynamicSharedMemorySize,
                             AT_SMEM_BYTES);
        attrs_set = true;
    }

    float* xr_p;  cudaGetSymbolAddress((void**)&xr_p,  g_xr);
    float* wr_p;  cudaGetSymbolAddress((void**)&wr_p,  g_wr);
    float* pwr_p; cudaGetSymbolAddress((void**)&pwr_p, g_pwr);

    // 0. Pre-round GEMM inputs to TF32-exact fp32
    {
        int n4 = (M_ROWS * CH) / 4;
        round_tf32_kernel<<<(n4 + 255) / 256, 256>>>(x, xr_p, n4);
        n4 = (THREE_C * CH) / 4;
        round_tf32_kernel<<<(n4 + 255) / 256, 256>>>(qkv_w, wr_p, n4);
        n4 = (CH * CH) / 4;
        round_tf32_kernel<<<(n4 + 255) / 256, 256>>>(proj_w, pwr_p, n4);
    }
    // 1. QKV projection
    {
        dim3 grid(THREE_C / BN, M_ROWS / BM);
        qkv_gemm_kernel<<<grid, 256, GEMM_SMEM_BYTES>>>(q_bias, v_bias);
    }
    // 2. RPB gather
    {
        const int total = NH * SEQ * SEQ;
        rpb_gather_kernel<<<(total + 255) / 256, 256>>>(rpb_tab, relidx);
    }
    // 3. Attention (TF32 mma)
    {
        dim3 grid(BATCH * NH, 2);
        attn_mma_kernel<<<grid, 256, AT_SMEM_BYTES>>>();
    }
    // 4. Projection
    {
        dim3 grid(CH / BN, M_ROWS / BM);
        proj_gemm_kernel<<<grid, 256, GEMM_SMEM_BYTES>>>(proj_b, out);
    }
}

// round 6
// speedup vs baseline: 4.1618x; 1.3409x over previous
#include <cuda_runtime.h>
#include <cuda_bf16.h>

// Problem constants
#define BATCH 256
#define SEQ   196
#define CH    768
#define NH    12
#define HD    64
#define M_ROWS (BATCH * SEQ)       // 50176
#define THREE_C (3 * CH)           // 2304
#define SCALE 0.125f

// Scratch
__device__ float g_q[(size_t)BATCH * NH * SEQ * HD];   // [B,H,N,hd] (TF32-rounded)
__device__ float g_k[(size_t)BATCH * NH * SEQ * HD];
__device__ float g_v[(size_t)BATCH * NH * SEQ * HD];
__device__ float g_rpb[(size_t)NH * SEQ * SEQ];        // [H,N,N]
__device__ float g_att[(size_t)M_ROWS * CH];           // [B,N,C] (TF32-rounded)
__device__ float g_xr[(size_t)M_ROWS * CH];            // TF32-rounded x
__device__ float g_wr[(size_t)THREE_C * CH];           // TF32-rounded qkv_w
__device__ float g_pwr[(size_t)CH * CH];               // TF32-rounded proj_w

// ---------------------------------------------------------------------------
// PTX helpers
// ---------------------------------------------------------------------------
__device__ __forceinline__ void cp_async16(float* smem_ptr, const float* gmem_ptr) {
    unsigned saddr = (unsigned)__cvta_generic_to_shared(smem_ptr);
    asm volatile("cp.async.cg.shared.global [%0], [%1], 16;\n"
                 :: "r"(saddr), "l"(gmem_ptr));
}
__device__ __forceinline__ void cp_commit() {
    asm volatile("cp.async.commit_group;\n");
}
template <int N>
__device__ __forceinline__ void cp_wait() {
    asm volatile("cp.async.wait_group %0;\n" :: "n"(N));
}
__device__ __forceinline__ unsigned f2tf32(float x) {
    unsigned r;
    asm("cvt.rna.tf32.f32 %0, %1;\n" : "=r"(r) : "f"(x));
    return r;
}
__device__ __forceinline__ float tf32_round(float x) {
    return __uint_as_float(f2tf32(x));
}
__device__ __forceinline__ void mma_tf32(float c[4], unsigned a0, unsigned a1,
                                         unsigned a2, unsigned a3,
                                         unsigned b0, unsigned b1) {
    asm volatile(
        "mma.sync.aligned.m16n8k8.row.col.f32.tf32.tf32.f32 "
        "{%0,%1,%2,%3}, {%4,%5,%6,%7}, {%8,%9}, {%0,%1,%2,%3};\n"
        : "+f"(c[0]), "+f"(c[1]), "+f"(c[2]), "+f"(c[3])
        : "r"(a0), "r"(a1), "r"(a2), "r"(a3), "r"(b0), "r"(b1));
}

// ---------------------------------------------------------------------------
// Kernel 0: elementwise TF32 rounding
// ---------------------------------------------------------------------------
__global__ void round_tf32_kernel(const float* __restrict__ src,
                                  float* __restrict__ dst, int n4)
{
    int i = blockIdx.x * blockDim.x + threadIdx.x;
    if (i >= n4) return;
    float4 v = ((const float4*)src)[i];
    v.x = tf32_round(v.x); v.y = tf32_round(v.y);
    v.z = tf32_round(v.z); v.w = tf32_round(v.w);
    ((float4*)dst)[i] = v;
}

// ---------------------------------------------------------------------------
// TF32 mma GEMM mainloop, 3-stage cp.async pipeline
// ---------------------------------------------------------------------------
#define BM 128
#define BN 128
#define BK 32
#define NSTAGE 3
#define SMEM_STAGE_FLOATS (BM * BK + BN * BK)             // 8192
#define GEMM_SMEM_BYTES (NSTAGE * SMEM_STAGE_FLOATS * 4)  // 98304

__device__ __forceinline__
void gemm_mainloop(const float* __restrict__ Aptr,
                   const float* __restrict__ Bptr,
                   float* sm, int tid, float acc[4][4][4])
{
    const int warp = tid >> 5;
    const int lane = tid & 31;
    const int g  = lane >> 2;
    const int tg = lane & 3;
    const int wr = warp & 1;
    const int wc = warp >> 1;

    const int ldr = tid >> 3;
    const int ldc = tid & 7;

    #pragma unroll
    for (int i = 0; i < 4; i++)
        #pragma unroll
        for (int j = 0; j < 4; j++)
            #pragma unroll
            for (int t = 0; t < 4; t++) acc[i][j][t] = 0.f;

    auto prefetch = [&](int stage, int k0) {
        float* As = sm + stage * SMEM_STAGE_FLOATS;
        float* Bs = As + BM * BK;
        #pragma unroll
        for (int p = 0; p < 4; p++) {
            const int row = p * 32 + ldr;
            const int sc = (ldc ^ (row & 7)) << 2;
            cp_async16(As + row * BK + sc, Aptr + (size_t)row * CH + k0 + ldc * 4);
            cp_async16(Bs + row * BK + sc, Bptr + (size_t)row * CH + k0 + ldc * 4);
        }
    };

    prefetch(0, 0);      cp_commit();
    prefetch(1, BK);     cp_commit();

    const int NKT = CH / BK;     // 24
    int sC = 0;                  // compute stage
    int sF = 2;                  // fetch stage

    #pragma unroll 1
    for (int kt = 0; kt < NKT; kt++) {
        cp_wait<1>();
        __syncthreads();

        if (kt + 2 < NKT) prefetch(sF, (kt + 2) * BK);
        cp_commit();   // commit every iter (possibly empty) to keep wait<1> exact

        const float* As = sm + sC * SMEM_STAGE_FLOATS;
        const float* Bs = As + BM * BK;

        const float* Arow0 = As + (wr * 64 + g) * BK;
        const float* Brow  = Bs + (wc * 32 + g) * BK;

        #pragma unroll
        for (int ks = 0; ks < 4; ks++) {
            const int ca = 2 * ks;
            const int c0 = ((ca ^ g) << 2) + tg;
            const int c1 = (((ca + 1) ^ g) << 2) + tg;
            unsigned a[4][4], b[4][2];
            #pragma unroll
            for (int mi = 0; mi < 4; mi++) {
                const float* p0 = Arow0 + mi * 16 * BK;
                const float* p1 = p0 + 8 * BK;
                a[mi][0] = __float_as_uint(p0[c0]);
                a[mi][1] = __float_as_uint(p1[c0]);
                a[mi][2] = __float_as_uint(p0[c1]);
                a[mi][3] = __float_as_uint(p1[c1]);
            }
            #pragma unroll
            for (int ni = 0; ni < 4; ni++) {
                const float* pn = Brow + ni * 8 * BK;
                b[ni][0] = __float_as_uint(pn[c0]);
                b[ni][1] = __float_as_uint(pn[c1]);
            }
            #pragma unroll
            for (int mi = 0; mi < 4; mi++)
                #pragma unroll
                for (int ni = 0; ni < 4; ni++)
                    mma_tf32(acc[mi][ni], a[mi][0], a[mi][1], a[mi][2], a[mi][3],
                             b[ni][0], b[ni][1]);
        }
        sC = (sC + 1 == NSTAGE) ? 0 : sC + 1;
        sF = (sF + 1 == NSTAGE) ? 0 : sF + 1;
    }
}

// ---------------------------------------------------------------------------
// Kernel 1: fused QKV projection
// ---------------------------------------------------------------------------
__global__ __launch_bounds__(256, 2)
void qkv_gemm_kernel(const float* __restrict__ qb,
                     const float* __restrict__ vb)
{
    extern __shared__ float sm[];
    const int bn = blockIdx.x;
    const int bm = blockIdx.y;
    const int tid = threadIdx.x;

    float acc[4][4][4];
    gemm_mainloop(g_xr + (size_t)(bm * BM) * CH, g_wr + (size_t)(bn * BN) * CH,
                  sm, tid, acc);

    const int warp = tid >> 5;
    const int lane = tid & 31;
    const int g = lane >> 2, tg = lane & 3;
    const int wr = warp & 1, wc = warp >> 1;

    const int jblock = bn * BN;
    const int which = jblock / CH;

    #pragma unroll
    for (int mi = 0; mi < 4; mi++) {
        #pragma unroll
        for (int ni = 0; ni < 4; ni++) {
            const int jl = wc * 32 + ni * 8 + tg * 2;
            const int cbase = jblock + jl - which * CH;
            const int h = cbase >> 6;
            const int d = cbase & 63;
            #pragma unroll
            for (int rr = 0; rr < 2; rr++) {
                const int i = bm * BM + wr * 64 + mi * 16 + g + rr * 8;
                const int b = i / SEQ;
                const int n = i - b * SEQ;
                const size_t base = (((size_t)(b * NH + h)) * SEQ + n) * HD + d;
                const float v0 = acc[mi][ni][rr * 2 + 0];
                const float v1 = acc[mi][ni][rr * 2 + 1];
                float2 out;
                if (which == 0) {
                    float2 qb2 = *(const float2*)(qb + cbase);
                    out.x = tf32_round((v0 + qb2.x) * SCALE);
                    out.y = tf32_round((v1 + qb2.y) * SCALE);
                    *(float2*)(g_q + base) = out;
                } else if (which == 1) {
                    out.x = tf32_round(v0); out.y = tf32_round(v1);
                    *(float2*)(g_k + base) = out;
                } else {
                    float2 vb2 = *(const float2*)(vb + cbase);
                    out.x = tf32_round(v0 + vb2.x);
                    out.y = tf32_round(v1 + vb2.y);
                    *(float2*)(g_v + base) = out;
                }
            }
        }
    }
}

// ---------------------------------------------------------------------------
// Kernel 2: rpb gather
// ---------------------------------------------------------------------------
__global__ void rpb_gather_kernel(const float* __restrict__ table,
                                  const int* __restrict__ relidx)
{
    int idx = blockIdx.x * blockDim.x + threadIdx.x;
    const int total = NH * SEQ * SEQ;
    if (idx >= total) return;
    int ij = idx % (SEQ * SEQ);
    int h  = idx / (SEQ * SEQ);
    g_rpb[idx] = table[relidx[ij] * NH + h];
}

// ---------------------------------------------------------------------------
// Kernel 3: TF32 mma attention. One CTA per (b,h); loops over 2 m-tiles.
// K/V staged once. 8 warps x 16-row strips.
// ---------------------------------------------------------------------------
#define AT_LDQ 68
#define AT_LDK 68
#define AT_LDV 72
#define AT_LDP 200
#define AT_K_OFF 25600          // P region = [128][200] floats (overlays Q)
#define AT_V_OFF (AT_K_OFF + 200 * AT_LDK)
#define AT_SMEM_FLOATS (AT_V_OFF + 200 * AT_LDV)
#define AT_SMEM_BYTES (AT_SMEM_FLOATS * 4)   // 214400

__global__ __launch_bounds__(256, 1)
void attn_mma_kernel()
{
    extern __shared__ float sm[];
    float* P = sm;               // [128][AT_LDP]
    float* Qs = sm;              // [128][AT_LDQ]
    float* Ks = sm + AT_K_OFF;   // [200][AT_LDK]
    float* Vs = sm + AT_V_OFF;   // [200][AT_LDV]

    const int bh = blockIdx.x;
    const int b = bh / NH;
    const int h = bh % NH;
    const int tid = threadIdx.x;
    const int warp = tid >> 5;
    const int lane = tid & 31;
    const int g = lane >> 2;
    const int tg = lane & 3;

    const float* Qg = g_q + (size_t)bh * SEQ * HD;
    const float* Kg = g_k + (size_t)bh * SEQ * HD;
    const float* Vg = g_v + (size_t)bh * SEQ * HD;

    const float4 z4 = make_float4(0.f, 0.f, 0.f, 0.f);

    // stage K and V once (cp.async; zero the pad rows 196..199)
    for (int t = tid; t < 200 * 16; t += 256) {
        const int r = t >> 4, c = (t & 15) << 2;
        if (r < SEQ) {
            cp_async16(Ks + r * AT_LDK + c, Kg + r * HD + c);
            cp_async16(Vs + r * AT_LDV + c, Vg + r * HD + c);
        } else {
            *(float4*)(Ks + r * AT_LDK + c) = z4;
            *(float4*)(Vs + r * AT_LDV + c) = z4;
        }
    }
    cp_commit();

    const float* rpb_base = g_rpb + (size_t)h * SEQ * SEQ;
    float* attbase = g_att + (size_t)b * SEQ * CH + h * HD;

    #pragma unroll 1
    for (int mt = 0; mt < 2; mt++) {
        const int qbase = mt * 128;
        const int qrows = mt ? (SEQ - 128) : 128;

        // stage Q tile (P/Q region free: first iter trivially, later after sync)
        __syncthreads();
        for (int t = tid; t < 128 * 16; t += 256) {
            const int r = t >> 4, c = (t & 15) << 2;
            if (r < qrows)
                cp_async16(Qs + r * AT_LDQ + c, Qg + (qbase + r) * HD + c);
            else
                *(float4*)(Qs + r * AT_LDQ + c) = z4;
        }
        cp_commit();
        cp_wait<0>();
        __syncthreads();

        // ---- Phase 1: S = Q @ K^T ----
        const int r0 = warp * 16;
        float acc[25][4];
        #pragma unroll
        for (int t = 0; t < 25; t++)
            #pragma unroll
            for (int e = 0; e < 4; e++) acc[t][e] = 0.f;

        #pragma unroll
        for (int ks = 0; ks < 8; ks++) {
            const int k0 = ks * 8;
            const unsigned a0 = __float_as_uint(Qs[(r0 + g) * AT_LDQ + k0 + tg]);
            const unsigned a1 = __float_as_uint(Qs[(r0 + g + 8) * AT_LDQ + k0 + tg]);
            const unsigned a2 = __float_as_uint(Qs[(r0 + g) * AT_LDQ + k0 + tg + 4]);
            const unsigned a3 = __float_as_uint(Qs[(r0 + g + 8) * AT_LDQ + k0 + tg + 4]);
            #pragma unroll
            for (int t = 0; t < 25; t++) {
                const unsigned b0 = __float_as_uint(Ks[(t * 8 + g) * AT_LDK + k0 + tg]);
                const unsigned b1 = __float_as_uint(Ks[(t * 8 + g) * AT_LDK + k0 + tg + 4]);
                mma_tf32(acc[t], a0, a1, a2, a3, b0, b1);
            }
        }
        __syncthreads();   // all Q reads done (P overlays Q)

        // ---- rpb add + masking ----
        const int rlo = qbase + r0 + g;
        const int rhi = rlo + 8;
        const float* rp_lo = rpb_base + (size_t)min(rlo, SEQ - 1) * SEQ;
        const float* rp_hi = rpb_base + (size_t)min(rhi, SEQ - 1) * SEQ;
        #pragma unroll
        for (int t = 0; t < 25; t++) {
            const int c0 = t * 8 + 2 * tg;
            const int c1 = c0 + 1;
            if (c0 < SEQ) { acc[t][0] += __ldg(rp_lo + c0); acc[t][2] += __ldg(rp_hi + c0); }
            else          { acc[t][0] = -1e30f;             acc[t][2] = -1e30f; }
            if (c1 < SEQ) { acc[t][1] += __ldg(rp_lo + c1); acc[t][3] += __ldg(rp_hi + c1); }
            else          { acc[t][1] = -1e30f;             acc[t][3] = -1e30f; }
        }

        // ---- softmax ----
        float mlo = -1e30f, mhi = -1e30f;
        #pragma unroll
        for (int t = 0; t < 25; t++) {
            mlo = fmaxf(mlo, fmaxf(acc[t][0], acc[t][1]));
            mhi = fmaxf(mhi, fmaxf(acc[t][2], acc[t][3]));
        }
        mlo = fmaxf(mlo, __shfl_xor_sync(0xffffffffu, mlo, 1));
        mlo = fmaxf(mlo, __shfl_xor_sync(0xffffffffu, mlo, 2));
        mhi = fmaxf(mhi, __shfl_xor_sync(0xffffffffu, mhi, 1));
        mhi = fmaxf(mhi, __shfl_xor_sync(0xffffffffu, mhi, 2));

        float llo = 0.f, lhi = 0.f;
        float* Prow_lo = P + (r0 + g) * AT_LDP;
        float* Prow_hi = P + (r0 + g + 8) * AT_LDP;
        #pragma unroll
        for (int t = 0; t < 25; t++) {
            const int c0 = t * 8 + 2 * tg;
            const float p0 = tf32_round(__expf(acc[t][0] - mlo));
            const float p1 = tf32_round(__expf(acc[t][1] - mlo));
            const float p2 = tf32_round(__expf(acc[t][2] - mhi));
            const float p3 = tf32_round(__expf(acc[t][3] - mhi));
            llo += p0 + p1;
            lhi += p2 + p3;
            Prow_lo[c0] = p0; Prow_lo[c0 + 1] = p1;
            Prow_hi[c0] = p2; Prow_hi[c0 + 1] = p3;
        }
        llo += __shfl_xor_sync(0xffffffffu, llo, 1);
        llo += __shfl_xor_sync(0xffffffffu, llo, 2);
        lhi += __shfl_xor_sync(0xffffffffu, lhi, 1);
        lhi += __shfl_xor_sync(0xffffffffu, lhi, 2);
        const float inv_lo = 1.f / llo;
        const float inv_hi = 1.f / lhi;

        __syncwarp();   // own P rows complete (only own rows are read back)

        // ---- Phase 2: O = P @ V ----
        float oacc[8][4];
        #pragma unroll
        for (int nt = 0; nt < 8; nt++)
            #pragma unroll
            for (int e = 0; e < 4; e++) oacc[nt][e] = 0.f;

        #pragma unroll
        for (int kt = 0; kt < 25; kt++) {
            const int k0 = kt * 8;
            const unsigned a0 = __float_as_uint(Prow_lo[k0 + tg]);
            const unsigned a1 = __float_as_uint(Prow_hi[k0 + tg]);
            const unsigned a2 = __float_as_uint(Prow_lo[k0 + tg + 4]);
            const unsigned a3 = __float_as_uint(Prow_hi[k0 + tg + 4]);
            #pragma unroll
            for (int nt = 0; nt < 8; nt++) {
                const unsigned b0 = __float_as_uint(Vs[(k0 + tg) * AT_LDV + nt * 8 + g]);
                const unsigned b1 = __float_as_uint(Vs[(k0 + tg + 4) * AT_LDV + nt * 8 + g]);
                mma_tf32(oacc[nt], a0, a1, a2, a3, b0, b1);
            }
        }

        // ---- store O ----
        #pragma unroll
        for (int nt = 0; nt < 8; nt++) {
            const int c = nt * 8 + 2 * tg;
            if (rlo < SEQ) {
                float2 o2;
                o2.x = tf32_round(oacc[nt][0] * inv_lo);
                o2.y = tf32_round(oacc[nt][1] * inv_lo);
                *(float2*)(attbase + (size_t)rlo * CH + c) = o2;
            }
            if (rhi < SEQ) {
                float2 o2;
                o2.x = tf32_round(oacc[nt][2] * inv_hi);
                o2.y = tf32_round(oacc[nt][3] * inv_hi);
                *(float2*)(attbase + (size_t)rhi * CH + c) = o2;
            }
        }
    }
}

// ---------------------------------------------------------------------------
// Kernel 4: output projection
// ---------------------------------------------------------------------------
__global__ __launch_bounds__(256, 2)
void proj_gemm_kernel(const float* __restrict__ pb,
                      float* __restrict__ out)
{
    extern __shared__ float sm[];
    const int bn = blockIdx.x;
    const int bm = blockIdx.y;
    const int tid = threadIdx.x;

    float acc[4][4][4];
    gemm_mainloop(g_att + (size_t)(bm * BM) * CH, g_pwr + (size_t)(bn * BN) * CH,
                  sm, tid, acc);

    const int warp = tid >> 5;
    const int lane = tid & 31;
    const int g = lane >> 2, tg = lane & 3;
    const int wr = warp & 1, wc = warp >> 1;

    #pragma unroll
    for (int mi = 0; mi < 4; mi++) {
        #pragma unroll
        for (int ni = 0; ni < 4; ni++) {
            const int j = bn * BN + wc * 32 + ni * 8 + tg * 2;
            const float2 pb2 = *(const float2*)(pb + j);
            #pragma unroll
            for (int rr = 0; rr < 2; rr++) {
                const int i = bm * BM + wr * 64 + mi * 16 + g + rr * 8;
                float2 o2;
                o2.x = acc[mi][ni][rr * 2 + 0] + pb2.x;
                o2.y = acc[mi][ni][rr * 2 + 1] + pb2.y;
                *(float2*)(out + (size_t)i * CH + j) = o2;
            }
        }
    }
}

// ---------------------------------------------------------------------------
// Launch
// ---------------------------------------------------------------------------
extern "C" void kernel_launch(void* const* d_in, const int* in_sizes, int n_in,
                              void* d_out, int out_size)
{
    const float* x       = (const float*)d_in[0];
    const float* qkv_w   = (const float*)d_in[1];
    const float* q_bias  = (const float*)d_in[2];
    const float* v_bias  = (const float*)d_in[3];
    const float* rpb_tab = (const float*)d_in[4];
    const float* proj_w  = (const float*)d_in[5];
    const float* proj_b  = (const float*)d_in[6];
    const int*   relidx  = (const int*)d_in[7];
    float*       out     = (float*)d_out;

    static bool attrs_set = false;
    if (!attrs_set) {
        cudaFuncSetAttribute(qkv_gemm_kernel,
                             cudaFuncAttributeMaxDynamicSharedMemorySize,
                             GEMM_SMEM_BYTES);
        cudaFuncSetAttribute(proj_gemm_kernel,
                             cudaFuncAttributeMaxDynamicSharedMemorySize,
                             GEMM_SMEM_BYTES);
        cudaFuncSetAttribute(attn_mma_kernel,
                             cudaFuncAttributeMaxDynamicSharedMemorySize,
                             AT_SMEM_BYTES);
        attrs_set = true;
    }

    float* xr_p;  cudaGetSymbolAddress((void**)&xr_p,  g_xr);
    float* wr_p;  cudaGetSymbolAddress((void**)&wr_p,  g_wr);
    float* pwr_p; cudaGetSymbolAddress((void**)&pwr_p, g_pwr);

    // 0. Pre-round GEMM inputs to TF32-exact fp32
    {
        int n4 = (M_ROWS * CH) / 4;
        round_tf32_kernel<<<(n4 + 255) / 256, 256>>>(x, xr_p, n4);
        n4 = (THREE_C * CH) / 4;
        round_tf32_kernel<<<(n4 + 255) / 256, 256>>>(qkv_w, wr_p, n4);
        n4 = (CH * CH) / 4;
        round_tf32_kernel<<<(n4 + 255) / 256, 256>>>(proj_w, pwr_p, n4);
    }
    // 1. QKV projection
    {
        dim3 grid(THREE_C / BN, M_ROWS / BM);
        qkv_gemm_kernel<<<grid, 256, GEMM_SMEM_BYTES>>>(q_bias, v_bias);
    }
    // 2. RPB gather
    {
        const int total = NH * SEQ * SEQ;
        rpb_gather_kernel<<<(total + 255) / 256, 256>>>(rpb_tab, relidx);
    }
    // 3. Attention (TF32 mma, one CTA per (b,h))
    {
        attn_mma_kernel<<<BATCH * NH, 256, AT_SMEM_BYTES>>>();
    }
    // 4. Projection
    {
        dim3 grid(CH / BN, M_ROWS / BM);
        proj_gemm_kernel<<<grid, 256, GEMM_SMEM_BYTES>>>(proj_b, out);
    }
}